// round 1
// baseline (speedup 1.0000x reference)
#include <cuda_runtime.h>

// out[n, d, t] = mean over d' of in[n, d', t]
// in: [32768, 64, 64] fp32 (N_AGENTS, FEAT_DIM, N_FRAMES)
// Each agent row is 64*64 = 4096 floats = 1024 float4.
// 16 threads per agent; thread owns one float4 (4 t-values), reduces over d.

static constexpr int N_AGENTS = 32768;
static constexpr int FEAT_DIM = 64;
static constexpr int QUADS_PER_ROW = 16;   // 64 t / 4
static constexpr int F4_PER_AGENT = 1024;  // 64*64/4

__global__ void __launch_bounds__(256)
mean_bcast_kernel(const float4* __restrict__ in, float4* __restrict__ out) {
    int gid = blockIdx.x * blockDim.x + threadIdx.x;   // 0 .. 32768*16-1
    int agent = gid >> 4;
    int tq = gid & 15;

    const float4* __restrict__ row = in + (size_t)agent * F4_PER_AGENT + tq;
    float4* __restrict__ orow = out + (size_t)agent * F4_PER_AGENT + tq;

    float ax = 0.f, ay = 0.f, az = 0.f, aw = 0.f;
    #pragma unroll 8
    for (int d = 0; d < FEAT_DIM; d++) {
        float4 v = row[d * QUADS_PER_ROW];
        ax += v.x; ay += v.y; az += v.z; aw += v.w;
    }
    const float inv = 1.0f / (float)FEAT_DIM;
    float4 m;
    m.x = ax * inv; m.y = ay * inv; m.z = az * inv; m.w = aw * inv;

    #pragma unroll 8
    for (int d = 0; d < FEAT_DIM; d++) {
        orow[d * QUADS_PER_ROW] = m;
    }
}

extern "C" void kernel_launch(void* const* d_in, const int* in_sizes, int n_in,
                              void* d_out, int out_size) {
    const float4* in = (const float4*)d_in[0];
    float4* out = (float4*)d_out;
    // seq_start_end (d_in[1]) is a no-op: contiguous partition, mean is per-agent.
    int total_threads = N_AGENTS * QUADS_PER_ROW;   // 524288
    int block = 256;
    int grid = total_threads / block;               // 2048
    mean_bcast_kernel<<<grid, block>>>(in, out);
}

// round 2
// speedup vs baseline: 1.0032x; 1.0032x over previous
#include <cuda_runtime.h>

// out[n, d, t] = mean over d' of in[n, d', t]
// in: [32768, 64, 64] fp32. Pure streaming: 512MB read + 512MB write.
// 16 threads per agent; thread owns one float4 (4 t-values), reduces over d.
// Streaming cache hints (.cs) on both load and store: every line touched
// exactly once, so evict-first policy keeps L2 clean for the DRAM scheduler.

static constexpr int N_AGENTS = 32768;
static constexpr int FEAT_DIM = 64;
static constexpr int QUADS_PER_ROW = 16;   // 64 t / 4
static constexpr int F4_PER_AGENT = 1024;  // 64*64/4

__global__ void __launch_bounds__(256)
mean_bcast_kernel(const float4* __restrict__ in, float4* __restrict__ out) {
    int gid = blockIdx.x * blockDim.x + threadIdx.x;   // 0 .. 32768*16-1
    int agent = gid >> 4;
    int tq = gid & 15;

    const float4* __restrict__ row = in + (size_t)agent * F4_PER_AGENT + tq;
    float4* __restrict__ orow = out + (size_t)agent * F4_PER_AGENT + tq;

    float ax = 0.f, ay = 0.f, az = 0.f, aw = 0.f;
    #pragma unroll 16
    for (int d = 0; d < FEAT_DIM; d++) {
        float4 v = __ldcs(&row[d * QUADS_PER_ROW]);
        ax += v.x; ay += v.y; az += v.z; aw += v.w;
    }
    const float inv = 1.0f / (float)FEAT_DIM;
    float4 m;
    m.x = ax * inv; m.y = ay * inv; m.z = az * inv; m.w = aw * inv;

    #pragma unroll 16
    for (int d = 0; d < FEAT_DIM; d++) {
        __stcs(&orow[d * QUADS_PER_ROW], m);
    }
}

extern "C" void kernel_launch(void* const* d_in, const int* in_sizes, int n_in,
                              void* d_out, int out_size) {
    const float4* in = (const float4*)d_in[0];
    float4* out = (float4*)d_out;
    // seq_start_end (d_in[1]) is a no-op: contiguous partition, mean is per-agent.
    int total_threads = N_AGENTS * QUADS_PER_ROW;   // 524288
    int block = 256;
    int grid = total_threads / block;               // 2048
    mean_bcast_kernel<<<grid, block>>>(in, out);
}